// round 1
// baseline (speedup 1.0000x reference)
#include <cuda_runtime.h>
#include <cuda_bf16.h>

// ---------------------------------------------------------------------------
// DGCNN encoder, restructured:
//   h[b,o,n,k] = A[b, idx[b,n,k], o] + (B2 - A)[b, n, o]
// with A = W1 @ X, B2 = W2 @ X  (K=27 factored out of the big GEMMs).
// BN+LeakyReLU applied post-max via per-channel affine (monotone).
// ---------------------------------------------------------------------------

#define B4   4
#define NPTS 256
#define KNN  27
#define MAXC 3072
#define XCATC 8160

__device__ float g_A[B4 * NPTS * MAXC];       // [b*256+n][o]
__device__ float g_B2[B4 * NPTS * MAXC];
__device__ float g_maxh[B4 * NPTS * MAXC];
__device__ float g_minh[B4 * NPTS * MAXC];
__device__ float g_sumh[B4 * NPTS * MAXC];
__device__ float g_sumsq[B4 * NPTS * MAXC];
__device__ float g_xcat[B4 * XCATC * NPTS];   // [b][c][n]
__device__ float g_st[2 * MAXC];              // scale, shift
__device__ float g_P0[B4 * 3 * NPTS];
__device__ float g_ypart[4 * B4 * 256 * NPTS]; // split-K partials for final GEMM
__device__ int   g_idx[B4 * NPTS * KNN];

// ---------------------------------------------------------------------------
// transpose x (4,256,3) -> P0 (4,3,256)
__global__ void xpose_kernel(const float* __restrict__ x, float* __restrict__ P0)
{
    int id = blockIdx.x * 256 + threadIdx.x;
    if (id >= B4 * 3 * NPTS) return;
    int b = id / (3 * NPTS);
    int r = id % (3 * NPTS);
    int c = r / NPTS;
    int n = r % NPTS;
    P0[id] = x[((long)b * NPTS + n) * 3 + c];
}

// ---------------------------------------------------------------------------
// KNN: per (b, i) select 27 smallest squared distances, tie -> smaller index
// grid (32, 4), block 256 (8 warps; warp w handles point i = bx*8+w)
__global__ void knn_kernel(const float* __restrict__ x, int* __restrict__ idxout)
{
    __shared__ float px[NPTS], py[NPTS], pz[NPTS];
    int b = blockIdx.y;
    int t = threadIdx.x;
    int w = t >> 5, lane = t & 31;
    {
        const float* xb = x + (long)b * NPTS * 3;
        px[t] = xb[t * 3 + 0];
        py[t] = xb[t * 3 + 1];
        pz[t] = xb[t * 3 + 2];
    }
    __syncthreads();
    int i = blockIdx.x * 8 + w;
    float xi = px[i], yi = py[i], zi = pz[i];
    float d[8];
#pragma unroll
    for (int m = 0; m < 8; m++) {
        int j = lane + 32 * m;
        float dx = xi - px[j], dy = yi - py[j], dz = zi - pz[j];
        d[m] = __fadd_rn(__fadd_rn(__fmul_rn(dx, dx), __fmul_rn(dy, dy)),
                         __fmul_rn(dz, dz));
    }
    for (int k = 0; k < KNN; k++) {
        float bv = d[0]; int bm = 0;
#pragma unroll
        for (int m = 1; m < 8; m++)
            if (d[m] < bv) { bv = d[m]; bm = m; }   // strict < keeps smallest j locally
        int bj = lane + 32 * bm;
#pragma unroll
        for (int off = 16; off > 0; off >>= 1) {
            float ov = __shfl_down_sync(0xffffffffu, bv, off);
            int   oj = __shfl_down_sync(0xffffffffu, bj, off);
            if (ov < bv || (ov == bv && oj < bj)) { bv = ov; bj = oj; }
        }
        bj = __shfl_sync(0xffffffffu, bj, 0);
        if (lane == 0) idxout[((long)b * NPTS + i) * KNN + k] = bj;
        if ((bj & 31) == lane) {
            int m = bj >> 5;
#pragma unroll
            for (int mm = 0; mm < 8; mm++)
                if (mm == m) d[mm] = 3.4e38f;       // predicated, keeps regs
        }
    }
}

// ---------------------------------------------------------------------------
// Generic GEMM: out[si*osplit + b*ob + n*on + o*oo] = sum_c P[b,c,n]*W[o, coff+c]
// P rows are length-256 (n contiguous), batch stride pstride.
// 64x64 tile, 256 threads, 4x4 per thread, BK=16. Optional split-K (S parts).
__global__ void gemm_kernel(const float* __restrict__ P, long pstride,
                            const float* __restrict__ W, int ldw, int coff,
                            float* __restrict__ out, long osplit, long ob, int on, int oo,
                            int Kc, int Cout, int S, int kchunk)
{
    int b  = blockIdx.z / S;
    int si = blockIdx.z % S;
    int kbeg = si * kchunk;
    int kend = min(Kc, kbeg + kchunk);
    int o0 = blockIdx.x * 64;
    int n0 = blockIdx.y * 64;
    const float* Pb = P + (long)b * pstride;

    __shared__ float sP[16][64];
    __shared__ float sW[16][68];

    int t = threadIdx.x;
    int tx = t & 15, ty = t >> 4;

    float acc[4][4];
#pragma unroll
    for (int i = 0; i < 4; i++)
#pragma unroll
        for (int j = 0; j < 4; j++) acc[i][j] = 0.f;

    for (int k0 = kbeg; k0 < kend; k0 += 16) {
#pragma unroll
        for (int i = 0; i < 4; i++) {
            int c = (t >> 6) + 4 * i;
            int n = t & 63;
            int cc = k0 + c;
            sP[c][n] = (cc < kend) ? Pb[(long)cc * NPTS + (n0 + n)] : 0.f;
        }
#pragma unroll
        for (int i = 0; i < 4; i++) {
            int id = t + 256 * i;
            int o = id >> 4;
            int c = id & 15;
            int og = o0 + o, cc = k0 + c;
            sW[c][o] = (og < Cout && cc < kend) ? W[(long)og * ldw + coff + cc] : 0.f;
        }
        __syncthreads();
#pragma unroll
        for (int k = 0; k < 16; k++) {
            float4 av = *reinterpret_cast<const float4*>(&sP[k][ty * 4]);
            float4 wv = *reinterpret_cast<const float4*>(&sW[k][tx * 4]);
            float a[4] = {av.x, av.y, av.z, av.w};
            float wr[4] = {wv.x, wv.y, wv.z, wv.w};
#pragma unroll
            for (int i = 0; i < 4; i++)
#pragma unroll
                for (int j = 0; j < 4; j++)
                    acc[i][j] = fmaf(a[i], wr[j], acc[i][j]);
        }
        __syncthreads();
    }
#pragma unroll
    for (int i = 0; i < 4; i++) {
        int n = n0 + ty * 4 + i;
#pragma unroll
        for (int j = 0; j < 4; j++) {
            int o = o0 + tx * 4 + j;
            if (o < Cout)
                out[(long)si * osplit + (long)b * ob + (long)n * on + (long)o * oo]
                    = acc[i][j];
        }
    }
}

// ---------------------------------------------------------------------------
// Gather over 27 neighbors: per (b,n,o) compute max/min/sum/sumsq of
// h_k = A[b, idx_k, o] + (B2 - A)[b, n, o]
__global__ void gather_kernel(const float* __restrict__ A, const float* __restrict__ B2,
                              const int* __restrict__ idx, int Cout,
                              float* __restrict__ maxh, float* __restrict__ minh,
                              float* __restrict__ sumh, float* __restrict__ sumsq)
{
    int bn = blockIdx.y;
    int b  = bn >> 8;
    int o  = blockIdx.x * blockDim.x + threadIdx.x;
    if (o >= Cout) return;
    const int* ip = idx + (long)bn * KNN;
    long base = (long)bn * Cout + o;
    float an = A[base];
    float Cn = B2[base] - an;
    float mx = -3.4e38f, mn = 3.4e38f, s = 0.f, s2 = 0.f;
    long bbase = (long)(b * NPTS) * Cout + o;
#pragma unroll
    for (int k = 0; k < KNN; k++) {
        float v = A[bbase + (long)ip[k] * Cout];
        mx = fmaxf(mx, v);
        mn = fminf(mn, v);
        s += v;
        s2 += v * v;
    }
    maxh[base]  = mx + Cn;
    minh[base]  = mn + Cn;
    sumh[base]  = s + 27.f * Cn;
    sumsq[base] = s2 + 2.f * Cn * s + 27.f * Cn * Cn;
}

// ---------------------------------------------------------------------------
// Per-channel BN stats over (b,n,k): M = 4*256*27; -> scale, shift
__global__ void stats_kernel(const float* __restrict__ sumh, const float* __restrict__ sumsq,
                             const float* __restrict__ g, const float* __restrict__ be,
                             int Cout, float* __restrict__ st)
{
    int o = blockIdx.x * 256 + threadIdx.x;
    if (o >= Cout) return;
    double s = 0.0, s2 = 0.0;
    for (int bn = 0; bn < B4 * NPTS; bn++) {
        s  += (double)sumh[(long)bn * Cout + o];
        s2 += (double)sumsq[(long)bn * Cout + o];
    }
    const double invM = 1.0 / (double)(B4 * NPTS * KNN);
    double mean = s * invM;
    double var  = s2 * invM - mean * mean;
    float sc = g[o] * rsqrtf((float)var + 1e-5f);
    float tr = be[o] - (float)mean * sc;
    st[o] = sc;
    st[Cout + o] = tr;
}

// ---------------------------------------------------------------------------
// Apply affine+lrelu to the k-extremum, build [exp ; temporal-mean(b=0)] into xcat.
// 32x32 (o,n) tile with smem transpose; block (32,8).
__global__ void finalize_kernel(const float* __restrict__ maxh, const float* __restrict__ minh,
                                const float* __restrict__ st, int Cout,
                                float* __restrict__ xcat, int outoff)
{
    __shared__ float T[B4][32][33];
    int o0 = blockIdx.x * 32, n0 = blockIdx.y * 32;
    int tx = threadIdx.x, ty = threadIdx.y;
    int o = o0 + tx;
    bool ov = (o < Cout);
    float sc = ov ? st[o] : 0.f;
    float tr = ov ? st[Cout + o] : 0.f;
    const float* src = (sc >= 0.f) ? maxh : minh;
#pragma unroll
    for (int b = 0; b < B4; b++) {
#pragma unroll
        for (int r = ty; r < 32; r += 8) {
            float vv = 0.f;
            if (ov) {
                int n = n0 + r;
                float h = src[(long)(b * NPTS + n) * Cout + o];
                float yv = fmaf(sc, h, tr);
                vv = (yv >= 0.f) ? yv : 0.2f * yv;
            }
            T[b][r][tx] = vv;
        }
    }
    __syncthreads();
#pragma unroll
    for (int r = ty; r < 32; r += 8) {
        int oc = o0 + r;
        if (oc < Cout) {
            int n = n0 + tx;
            float tp = 0.5f * (T[0][tx][r] + T[1][tx][r]);  // mean over t of batch 0
#pragma unroll
            for (int b = 0; b < B4; b++) {
                xcat[(long)b * (XCATC * NPTS) + (long)(outoff + oc) * NPTS + n] = T[b][tx][r];
                xcat[(long)b * (XCATC * NPTS) + (long)(outoff + Cout + oc) * NPTS + n] = tp;
            }
        }
    }
}

// ---------------------------------------------------------------------------
// Final: reduce 4 split-K partials, BN over (b,n) per channel, lrelu, store out.
// grid 256 blocks (one per o), 256 threads (one per n).
__global__ void final_bn_kernel(const float* __restrict__ yp, const float* __restrict__ g,
                                const float* __restrict__ be, float* __restrict__ out)
{
    int o = blockIdx.x, t = threadIdx.x;
    float v[B4];
    float s = 0.f, s2 = 0.f;
#pragma unroll
    for (int b = 0; b < B4; b++) {
        float xv = 0.f;
#pragma unroll
        for (int sp = 0; sp < 4; sp++)
            xv += yp[((long)(sp * B4 + b)) * 65536 + o * 256 + t];
        v[b] = xv;
        s += xv;
        s2 += xv * xv;
    }
    __shared__ float rs[256], rs2[256];
    rs[t] = s; rs2[t] = s2;
    __syncthreads();
    for (int off = 128; off > 0; off >>= 1) {
        if (t < off) { rs[t] += rs[t + off]; rs2[t] += rs2[t + off]; }
        __syncthreads();
    }
    float mean = rs[0] * (1.f / 1024.f);
    float var  = rs2[0] * (1.f / 1024.f) - mean * mean;
    float sc = g[o] * rsqrtf(var + 1e-5f);
    float tr = be[o] - mean * sc;
#pragma unroll
    for (int b = 0; b < B4; b++) {
        float yv = fmaf(sc, v[b], tr);
        out[(long)b * 65536 + o * 256 + t] = (yv >= 0.f) ? yv : 0.2f * yv;
    }
}

// ---------------------------------------------------------------------------
extern "C" void kernel_launch(void* const* d_in, const int* in_sizes, int n_in,
                              void* d_out, int out_size)
{
    const float* x = (const float*)d_in[0];
    const float* w[5]  = {(const float*)d_in[1], (const float*)d_in[4], (const float*)d_in[7],
                          (const float*)d_in[10], (const float*)d_in[13]};
    const float* gm[5] = {(const float*)d_in[2], (const float*)d_in[5], (const float*)d_in[8],
                          (const float*)d_in[11], (const float*)d_in[14]};
    const float* bt[5] = {(const float*)d_in[3], (const float*)d_in[6], (const float*)d_in[9],
                          (const float*)d_in[12], (const float*)d_in[15]};
    float* out = (float*)d_out;

    float *pA, *pB2, *pMax, *pMin, *pSum, *pSq, *pX, *pSt, *pP0, *pY;
    int* pIdx;
    cudaGetSymbolAddress((void**)&pA, g_A);
    cudaGetSymbolAddress((void**)&pB2, g_B2);
    cudaGetSymbolAddress((void**)&pMax, g_maxh);
    cudaGetSymbolAddress((void**)&pMin, g_minh);
    cudaGetSymbolAddress((void**)&pSum, g_sumh);
    cudaGetSymbolAddress((void**)&pSq, g_sumsq);
    cudaGetSymbolAddress((void**)&pX, g_xcat);
    cudaGetSymbolAddress((void**)&pSt, g_st);
    cudaGetSymbolAddress((void**)&pP0, g_P0);
    cudaGetSymbolAddress((void**)&pY, g_ypart);
    cudaGetSymbolAddress((void**)&pIdx, g_idx);

    xpose_kernel<<<12, 256>>>(x, pP0);
    knn_kernel<<<dim3(32, B4), 256>>>(x, pIdx);

    const int  Kc[4]   = {3, 96, 384, 1536};   // Cin_half per layer
    const int  Co[4]   = {48, 192, 768, 3072};
    const int  ldwv[4] = {6, 192, 768, 3072};
    const int  ioff[4] = {0, 0, 96, 480};      // xcat channel offset of layer input
    const int  ooff[4] = {0, 96, 480, 2016};   // xcat channel offset of layer output

    for (int L = 0; L < 4; L++) {
        const float* P = (L == 0) ? pP0 : (pX + (long)ioff[L] * NPTS);
        long pstride = (L == 0) ? (long)3 * NPTS : (long)XCATC * NPTS;
        dim3 gg((Co[L] + 63) / 64, 4, B4);
        // A = W1 @ X, B2 = W2 @ X  -> layout [b][n][o]
        gemm_kernel<<<gg, 256>>>(P, pstride, w[L], ldwv[L], 0,
                                 pA, 0, (long)NPTS * Co[L], Co[L], 1,
                                 Kc[L], Co[L], 1, Kc[L]);
        gemm_kernel<<<gg, 256>>>(P, pstride, w[L], ldwv[L], Kc[L],
                                 pB2, 0, (long)NPTS * Co[L], Co[L], 1,
                                 Kc[L], Co[L], 1, Kc[L]);
        gather_kernel<<<dim3((Co[L] + 255) / 256, B4 * NPTS), 256>>>(
            pA, pB2, pIdx, Co[L], pMax, pMin, pSum, pSq);
        stats_kernel<<<(Co[L] + 255) / 256, 256>>>(pSum, pSq, gm[L], bt[L], Co[L], pSt);
        finalize_kernel<<<dim3((Co[L] + 31) / 32, 8), dim3(32, 8)>>>(
            pMax, pMin, pSt, Co[L], pX, ooff[L]);
    }

    // Final projection: y[b,o,n] = sum_c xcat[b,c,n] * w4[o,c], split-K=4 partials
    gemm_kernel<<<dim3(4, 4, B4 * 4), 256>>>(pX, (long)XCATC * NPTS, w[4], XCATC, 0,
                                             pY, (long)B4 * 65536, 65536L, 1, 256,
                                             XCATC, 256, 4, 2040);
    final_bn_kernel<<<256, 256>>>(pY, gm[4], bt[4], out);
}

// round 2
// speedup vs baseline: 2.4690x; 2.4690x over previous
#include <cuda_runtime.h>

// ---------------------------------------------------------------------------
// DGCNN encoder on GB300.
//   h[b,o,n,k] = A[b, idx[b,n,k], o] + (B2 - A)[b, n, o],  A=W1@X, B2=W2@X
// Temporal-mean channels are batch-invariant -> computed once ("shared" GEMMs).
// BN+LeakyReLU applied post-max via per-channel affine (monotone).
// ---------------------------------------------------------------------------

#define B4    4
#define NPTS  256
#define KNN   27
#define MAXC  3072
#define VTOT  4080   // total "var" channels across layers: 48+192+768+3072

__device__ __align__(256) float g_A   [B4 * NPTS * MAXC];   // [b][n][o]
__device__ __align__(256) float g_B2  [B4 * NPTS * MAXC];
__device__ __align__(256) float g_Ash [4 * NPTS * MAXC];    // split-K partials
__device__ __align__(256) float g_Bsh [4 * NPTS * MAXC];
__device__ __align__(256) float g_maxh[B4 * NPTS * MAXC];
__device__ __align__(256) float g_minh[B4 * NPTS * MAXC];
__device__ __align__(256) float g_sumh[B4 * NPTS * MAXC];
__device__ __align__(256) float g_sumsq[B4 * NPTS * MAXC];
__device__ __align__(256) float g_Xvar[B4 * VTOT * NPTS];   // [b][vc][n]
__device__ __align__(256) float g_Xsh [VTOT * NPTS];        // [vc][n]
__device__ __align__(256) float g_w4v [256 * VTOT];
__device__ __align__(256) float g_w4s [256 * VTOT];
__device__ __align__(256) float g_ypv [8 * B4 * 256 * NPTS];
__device__ __align__(256) float g_yps [32 * 256 * NPTS];
__device__ __align__(256) float g_st  [2 * MAXC];
__device__ __align__(256) float g_P0  [B4 * 3 * NPTS];
__device__ __align__(256) int   g_idx [B4 * NPTS * KNN];

// ---------------------------------------------------------------------------
// transpose x (4,256,3) -> P0 (4,3,256)
__global__ void xpose_kernel(const float* __restrict__ x, float* __restrict__ P0)
{
    int id = blockIdx.x * 256 + threadIdx.x;
    if (id >= B4 * 3 * NPTS) return;
    int b = id / (3 * NPTS);
    int r = id % (3 * NPTS);
    int c = r / NPTS;
    int n = r % NPTS;
    P0[id] = x[((long)b * NPTS + n) * 3 + c];
}

// ---------------------------------------------------------------------------
// KNN: per (b,i) select 27 smallest squared distances, tie -> smaller index
__global__ void knn_kernel(const float* __restrict__ x, int* __restrict__ idxout)
{
    __shared__ float px[NPTS], py[NPTS], pz[NPTS];
    int b = blockIdx.y;
    int t = threadIdx.x;
    int w = t >> 5, lane = t & 31;
    {
        const float* xb = x + (long)b * NPTS * 3;
        px[t] = xb[t * 3 + 0];
        py[t] = xb[t * 3 + 1];
        pz[t] = xb[t * 3 + 2];
    }
    __syncthreads();
    int i = blockIdx.x * 8 + w;
    float xi = px[i], yi = py[i], zi = pz[i];
    float d[8];
#pragma unroll
    for (int m = 0; m < 8; m++) {
        int j = lane + 32 * m;
        float dx = xi - px[j], dy = yi - py[j], dz = zi - pz[j];
        d[m] = __fadd_rn(__fadd_rn(__fmul_rn(dx, dx), __fmul_rn(dy, dy)),
                         __fmul_rn(dz, dz));
    }
    for (int k = 0; k < KNN; k++) {
        float bv = d[0]; int bm = 0;
#pragma unroll
        for (int m = 1; m < 8; m++)
            if (d[m] < bv) { bv = d[m]; bm = m; }
        int bj = lane + 32 * bm;
#pragma unroll
        for (int off = 16; off > 0; off >>= 1) {
            float ov = __shfl_down_sync(0xffffffffu, bv, off);
            int   oj = __shfl_down_sync(0xffffffffu, bj, off);
            if (ov < bv || (ov == bv && oj < bj)) { bv = ov; bj = oj; }
        }
        bj = __shfl_sync(0xffffffffu, bj, 0);
        if (lane == 0) idxout[((long)b * NPTS + i) * KNN + k] = bj;
        if ((bj & 31) == lane) {
            int m = bj >> 5;
#pragma unroll
            for (int mm = 0; mm < 8; mm++)
                if (mm == m) d[mm] = 3.4e38f;
        }
    }
}

// ---------------------------------------------------------------------------
// GEMM: 128(M) x 64(N) tile, 256 threads, 8x4 per thread, BK=16, double-buffered.
// Row o' < Cout -> W row o' at column offset coffA, output outA;
// row o' >= Cout -> W row o'-Cout at coffB, output outB.
// Epilogue can add nAdd split-K partials from addA/addB ([s][n][Cout]).
// out[si*osplit + b*obatch + n*on + oi*oo].
__global__ __launch_bounds__(256, 2)
void gemm_kernel(const float* __restrict__ P, long pstride,
                 const float* __restrict__ W, int ldw, int coffA, int coffB,
                 int Cout, int Mrows, int Kc,
                 const float* __restrict__ addA, const float* __restrict__ addB,
                 int nAdd, long addstride,
                 float* __restrict__ outA, float* __restrict__ outB,
                 long osplit, long obatch, long on, long oo,
                 int S, int kchunk)
{
    int z  = blockIdx.z;
    int b  = z / S, si = z - b * S;
    int kbeg = si * kchunk;
    int kend = min(Kc, kbeg + kchunk);
    int o0 = blockIdx.x * 128, n0 = blockIdx.y * 64;
    int t  = threadIdx.x;
    int tx = t & 15, ty = t >> 4;

    __shared__ float sP[2][16][68];
    __shared__ float sW[2][16][132];

    float acc[4][8];
#pragma unroll
    for (int i = 0; i < 4; i++)
#pragma unroll
        for (int j = 0; j < 8; j++) acc[i][j] = 0.f;

    const float* Pb = P + (long)b * pstride;
    int pc = t >> 4;              // 0..15 (k row)
    int pn = n0 + (t & 15) * 4;   // n col (float4)

    float4 rp;
    float  rw[8];

    auto ldP = [&](int k0) {
        int c = k0 + pc;
        if (c < kend) rp = *(const float4*)(Pb + (long)c * NPTS + pn);
        else          rp = make_float4(0.f, 0.f, 0.f, 0.f);
    };
    auto ldW = [&](int k0) {
#pragma unroll
        for (int i = 0; i < 2; i++) {
            int id = t + 256 * i;
            int o  = o0 + (id >> 2);
            int c4 = (id & 3) * 4;
            bool orow = (o < Mrows);
            const float* wp = W + (orow ?
                ((long)((o < Cout) ? o : (o - Cout)) * ldw + ((o < Cout) ? coffA : coffB)) : 0);
#pragma unroll
            for (int j = 0; j < 4; j++) {
                int c = k0 + c4 + j;
                rw[i * 4 + j] = (orow && c < kend) ? wp[c] : 0.f;
            }
        }
    };
    auto stPW = [&](int buf) {
        *(float4*)&sP[buf][pc][(t & 15) * 4] = rp;
#pragma unroll
        for (int i = 0; i < 2; i++) {
            int id = t + 256 * i;
            int o  = id >> 2;
            int c4 = (id & 3) * 4;
#pragma unroll
            for (int j = 0; j < 4; j++) sW[buf][c4 + j][o] = rw[i * 4 + j];
        }
    };

    ldP(kbeg); ldW(kbeg);
    stPW(0);
    __syncthreads();
    int buf = 0;
    for (int k0 = kbeg; k0 < kend; k0 += 16) {
        bool nx = (k0 + 16) < kend;
        if (nx) { ldP(k0 + 16); ldW(k0 + 16); }
#pragma unroll
        for (int k = 0; k < 16; k++) {
            float4 a  = *(const float4*)&sP[buf][k][ty * 4];
            float4 b0 = *(const float4*)&sW[buf][k][tx * 4];
            float4 b1 = *(const float4*)&sW[buf][k][64 + tx * 4];
            float av[4] = {a.x, a.y, a.z, a.w};
            float bv[8] = {b0.x, b0.y, b0.z, b0.w, b1.x, b1.y, b1.z, b1.w};
#pragma unroll
            for (int i = 0; i < 4; i++)
#pragma unroll
                for (int j = 0; j < 8; j++)
                    acc[i][j] = fmaf(av[i], bv[j], acc[i][j]);
        }
        if (nx) stPW(buf ^ 1);
        __syncthreads();
        buf ^= 1;
    }

#pragma unroll
    for (int i = 0; i < 4; i++) {
        int n = n0 + ty * 4 + i;
#pragma unroll
        for (int j = 0; j < 8; j++) {
            int o = o0 + tx * 4 + (j & 3) + (j >> 2) * 64;
            if (o >= Mrows) continue;
            bool isA = (o < Cout);
            int  oi  = isA ? o : o - Cout;
            float v = acc[i][j];
            const float* ap = isA ? addA : addB;
            for (int s = 0; s < nAdd; s++)
                v += ap[(long)s * addstride + (long)n * Cout + oi];
            float* op = isA ? outA : outB;
            op[(long)si * osplit + (long)b * obatch + (long)n * on + (long)oi * oo] = v;
        }
    }
}

// ---------------------------------------------------------------------------
// Gather over 27 neighbors: per (b,n,o) max/min/sum/sumsq of
// h_k = A[b, idx_k, o] + (B2 - A)[b, n, o]
__global__ void gather_kernel(const float* __restrict__ A, const float* __restrict__ B2,
                              const int* __restrict__ idx, int Cout,
                              float* __restrict__ maxh, float* __restrict__ minh,
                              float* __restrict__ sumh, float* __restrict__ sumsq)
{
    int bn = blockIdx.y;
    int b  = bn >> 8;
    int o  = blockIdx.x * blockDim.x + threadIdx.x;
    if (o >= Cout) return;
    const int* ip = idx + (long)bn * KNN;
    long base = (long)bn * Cout + o;
    float an = A[base];
    float Cn = B2[base] - an;
    float mx = -3.4e38f, mn = 3.4e38f, s = 0.f, s2 = 0.f;
    long bbase = (long)(b * NPTS) * Cout + o;
#pragma unroll
    for (int k = 0; k < KNN; k++) {
        float v = A[bbase + (long)ip[k] * Cout];
        mx = fmaxf(mx, v);
        mn = fminf(mn, v);
        s += v;
        s2 += v * v;
    }
    maxh[base]  = mx + Cn;
    minh[base]  = mn + Cn;
    sumh[base]  = s + 27.f * Cn;
    sumsq[base] = s2 + 2.f * Cn * s + 27.f * Cn * Cn;
}

// ---------------------------------------------------------------------------
// Per-channel BN stats -> scale, shift.  64 channels/block, 4-way bn split.
__global__ void stats_kernel(const float* __restrict__ sumh, const float* __restrict__ sumsq,
                             const float* __restrict__ g, const float* __restrict__ be,
                             int Cout, float* __restrict__ st)
{
    __shared__ float ss[256], ss2[256];
    int l  = threadIdx.x & 63;
    int gq = threadIdx.x >> 6;
    int o  = blockIdx.x * 64 + l;
    float s = 0.f, s2 = 0.f;
    if (o < Cout) {
        for (int bn = gq; bn < B4 * NPTS; bn += 4) {
            long ix = (long)bn * Cout + o;
            s  += sumh[ix];
            s2 += sumsq[ix];
        }
    }
    ss[threadIdx.x] = s; ss2[threadIdx.x] = s2;
    __syncthreads();
    if (gq == 0 && o < Cout) {
        double S  = (double)ss[l]  + ss[l + 64]  + ss[l + 128]  + ss[l + 192];
        double S2 = (double)ss2[l] + ss2[l + 64] + ss2[l + 128] + ss2[l + 192];
        const double invM = 1.0 / (double)(B4 * NPTS * KNN);
        double mean = S * invM;
        double var  = S2 * invM - mean * mean;
        float sc = g[o] * rsqrtf((float)var + 1e-5f);
        st[o] = sc;
        st[Cout + o] = be[o] - (float)mean * sc;
    }
}

// ---------------------------------------------------------------------------
// Apply affine+lrelu to the k-extremum; write exp -> Xvar[b], tp -> Xsh.
__global__ void finalize_kernel(const float* __restrict__ maxh, const float* __restrict__ minh,
                                const float* __restrict__ st, int Cout,
                                float* __restrict__ Xvar, float* __restrict__ Xsh, int voff)
{
    __shared__ float T[B4][32][33];
    int o0 = blockIdx.x * 32, n0 = blockIdx.y * 32;
    int tx = threadIdx.x, ty = threadIdx.y;
    int o = o0 + tx;
    bool ov = (o < Cout);
    float sc = ov ? st[o] : 0.f;
    float tr = ov ? st[Cout + o] : 0.f;
    const float* src = (sc >= 0.f) ? maxh : minh;
#pragma unroll
    for (int b = 0; b < B4; b++) {
#pragma unroll
        for (int r = ty; r < 32; r += 8) {
            float vv = 0.f;
            if (ov) {
                int n = n0 + r;
                float h = src[(long)(b * NPTS + n) * Cout + o];
                float yv = fmaf(sc, h, tr);
                vv = (yv >= 0.f) ? yv : 0.2f * yv;
            }
            T[b][r][tx] = vv;
        }
    }
    __syncthreads();
#pragma unroll
    for (int r = ty; r < 32; r += 8) {
        int oc = o0 + r;
        if (oc < Cout) {
            int n = n0 + tx;
            float tp = 0.5f * (T[0][tx][r] + T[1][tx][r]);
#pragma unroll
            for (int b = 0; b < B4; b++)
                Xvar[((long)b * VTOT + voff + oc) * NPTS + n] = T[b][tx][r];
            Xsh[(long)(voff + oc) * NPTS + n] = tp;
        }
    }
}

// ---------------------------------------------------------------------------
// Permute w4 columns into var / shared blocks.
__global__ void w4perm_kernel(const float* __restrict__ w4,
                              float* __restrict__ w4v, float* __restrict__ w4s)
{
    int id = blockIdx.x * 256 + threadIdx.x;
    if (id >= 256 * VTOT) return;
    int o = id / VTOT, vc = id - o * VTOT;
    int CL, off4, voff;
    if (vc < 48)        { CL = 48;   off4 = 0;    voff = 0;    }
    else if (vc < 240)  { CL = 192;  off4 = 96;   voff = 48;   }
    else if (vc < 1008) { CL = 768;  off4 = 480;  voff = 240;  }
    else                { CL = 3072; off4 = 2016; voff = 1008; }
    int c = vc - voff;
    w4v[(long)o * VTOT + vc] = w4[(long)o * 8160 + off4 + c];
    w4s[(long)o * VTOT + vc] = w4[(long)o * 8160 + off4 + CL + c];
}

// ---------------------------------------------------------------------------
// Sum split-K partials (8 var + 32 shared), BN over (b,n), lrelu, store.
__global__ void final_bn_kernel(const float* __restrict__ ypv, const float* __restrict__ yps,
                                const float* __restrict__ g, const float* __restrict__ be,
                                float* __restrict__ out)
{
    int o = blockIdx.x, t = threadIdx.x;
    float sh = 0.f;
#pragma unroll
    for (int sp = 0; sp < 32; sp++) sh += yps[(long)sp * 65536 + o * 256 + t];
    float v[B4];
    float s = 0.f, s2 = 0.f;
#pragma unroll
    for (int b = 0; b < B4; b++) {
        float xv = sh;
#pragma unroll
        for (int sp = 0; sp < 8; sp++)
            xv += ypv[(long)sp * 262144 + b * 65536 + o * 256 + t];
        v[b] = xv;
        s += xv;
        s2 += xv * xv;
    }
    __shared__ float rs[256], rs2[256];
    rs[t] = s; rs2[t] = s2;
    __syncthreads();
    for (int off = 128; off > 0; off >>= 1) {
        if (t < off) { rs[t] += rs[t + off]; rs2[t] += rs2[t + off]; }
        __syncthreads();
    }
    float mean = rs[0] * (1.f / 1024.f);
    float var  = rs2[0] * (1.f / 1024.f) - mean * mean;
    float sc = g[o] * rsqrtf(var + 1e-5f);
    float tr = be[o] - mean * sc;
#pragma unroll
    for (int b = 0; b < B4; b++) {
        float yv = fmaf(sc, v[b], tr);
        out[(long)b * 65536 + o * 256 + t] = (yv >= 0.f) ? yv : 0.2f * yv;
    }
}

// ---------------------------------------------------------------------------
extern "C" void kernel_launch(void* const* d_in, const int* in_sizes, int n_in,
                              void* d_out, int out_size)
{
    const float* x = (const float*)d_in[0];
    const float* w[5]  = {(const float*)d_in[1], (const float*)d_in[4], (const float*)d_in[7],
                          (const float*)d_in[10], (const float*)d_in[13]};
    const float* gm[5] = {(const float*)d_in[2], (const float*)d_in[5], (const float*)d_in[8],
                          (const float*)d_in[11], (const float*)d_in[14]};
    const float* bt[5] = {(const float*)d_in[3], (const float*)d_in[6], (const float*)d_in[9],
                          (const float*)d_in[12], (const float*)d_in[15]};
    float* out = (float*)d_out;

    float *pA, *pB2, *pAsh, *pBsh, *pMax, *pMin, *pSum, *pSq;
    float *pXvar, *pXsh, *pW4v, *pW4s, *pYpv, *pYps, *pSt, *pP0;
    int* pIdx;
    cudaGetSymbolAddress((void**)&pA, g_A);
    cudaGetSymbolAddress((void**)&pB2, g_B2);
    cudaGetSymbolAddress((void**)&pAsh, g_Ash);
    cudaGetSymbolAddress((void**)&pBsh, g_Bsh);
    cudaGetSymbolAddress((void**)&pMax, g_maxh);
    cudaGetSymbolAddress((void**)&pMin, g_minh);
    cudaGetSymbolAddress((void**)&pSum, g_sumh);
    cudaGetSymbolAddress((void**)&pSq, g_sumsq);
    cudaGetSymbolAddress((void**)&pXvar, g_Xvar);
    cudaGetSymbolAddress((void**)&pXsh, g_Xsh);
    cudaGetSymbolAddress((void**)&pW4v, g_w4v);
    cudaGetSymbolAddress((void**)&pW4s, g_w4s);
    cudaGetSymbolAddress((void**)&pYpv, g_ypv);
    cudaGetSymbolAddress((void**)&pYps, g_yps);
    cudaGetSymbolAddress((void**)&pSt, g_st);
    cudaGetSymbolAddress((void**)&pP0, g_P0);
    cudaGetSymbolAddress((void**)&pIdx, g_idx);

    xpose_kernel<<<12, 256>>>(x, pP0);
    knn_kernel<<<dim3(32, B4), 256>>>(x, pIdx);

    const int Co[4]   = {48, 192, 768, 3072};
    const int Cp[4]   = {0, 48, 192, 768};       // per-half input channels (L>=1)
    const int ldwv[4] = {6, 192, 768, 3072};
    const int voff[4] = {0, 48, 240, 1008};      // output var-channel offset
    const int Ssh[4]  = {0, 1, 4, 4};            // split-K of shared GEMM

    for (int L = 0; L < 4; L++) {
        int Cout = Co[L], M = 2 * Cout;
        int gx = (M + 127) / 128;
        if (L == 0) {
            gemm_kernel<<<dim3(gx, 4, B4), 256>>>(
                pP0, 768, w[0], 6, 0, 3, Cout, M, 3,
                nullptr, nullptr, 0, 0,
                pA, pB2, 0, (long)NPTS * Cout, Cout, 1, 1, 16);
        } else {
            int K = Cp[L], ldw = ldwv[L], S = Ssh[L];
            int kch = (K + S - 1) / S;
            // shared GEMM -> split-K partials
            gemm_kernel<<<dim3(gx, 4, S), 256>>>(
                pXsh + (long)voff[L - 1] * NPTS, 0,
                w[L], ldw, K, 3 * K, Cout, M, K,
                nullptr, nullptr, 0, 0,
                pAsh, pBsh, (long)NPTS * Cout, 0, Cout, 1, S, kch);
            // var GEMM (4 batches), epilogue adds shared partials
            gemm_kernel<<<dim3(gx, 4, B4), 256>>>(
                pXvar + (long)voff[L - 1] * NPTS, (long)VTOT * NPTS,
                w[L], ldw, 0, 2 * K, Cout, M, K,
                pAsh, pBsh, S, (long)NPTS * Cout,
                pA, pB2, 0, (long)NPTS * Cout, Cout, 1, 1, K);
        }
        gather_kernel<<<dim3((Cout + 255) / 256, B4 * NPTS), 256>>>(
            pA, pB2, pIdx, Cout, pMax, pMin, pSum, pSq);
        stats_kernel<<<(Cout + 63) / 64, 256>>>(pSum, pSq, gm[L], bt[L], Cout, pSt);
        finalize_kernel<<<dim3((Cout + 31) / 32, 8), dim3(32, 8)>>>(
            pMax, pMin, pSt, Cout, pXvar, pXsh, voff[L]);
    }

    w4perm_kernel<<<(256 * VTOT + 255) / 256, 256>>>(w[4], pW4v, pW4s);
    // final var projection: M=256, K=4080, S=8
    gemm_kernel<<<dim3(2, 4, B4 * 8), 256>>>(
        pXvar, (long)VTOT * NPTS, pW4v, VTOT, 0, 0,
        256, 256, VTOT, nullptr, nullptr, 0, 0,
        pYpv, pYpv, (long)B4 * 65536, 65536, 1, 256, 8, 510);
    // final shared projection: S=32
    gemm_kernel<<<dim3(2, 4, 32), 256>>>(
        pXsh, 0, pW4s, VTOT, 0, 0,
        256, 256, VTOT, nullptr, nullptr, 0, 0,
        pYps, pYps, 65536, 0, 1, 256, 32, 128);
    final_bn_kernel<<<256, 256>>>(pYpv, pYps, gm[4], bt[4], out);
}